// round 8
// baseline (speedup 1.0000x reference)
#include <cuda_runtime.h>
#include <cstdint>

// MoEGRU: B=256, L=1800, F=50, E=4, K=2, H=32, D=64, HU=32
#define NB 256
#define NL 1800
#define NF 50
#define NE 4
#define NH 32
#define ND 64
#define NS 512       // routed chains = B*K
#define RR 4         // recurrence pipeline batch (even, divides NL)
#define NK (NL / RR) // 450 super-steps
#define MAXP 260     // max chain pairs (512/2 + up to 4 odd-bucket pads)

typedef unsigned long long ull;

// ---- scratch (static device globals; no allocation allowed) ----
__device__ float g_M[NE * 96 * NF];             // fused W_in -> Wih0 matrix
__device__ float g_c[NS * 96];                  // per-chain constant (emb/bias folded)
__device__ int   g_ce[NS];                      // chain -> expert
__device__ float g_cw[NS];                      // chain -> routing weight
__device__ float g_predw[NS];                   // weighted per-chain prediction
__device__ int   g_pairA[MAXP], g_pairB[MAXP];  // same-expert chain pairs
__device__ int   g_npair;

// ---- packed f32x2 helpers (sm_103a dual-fp32 pipe) ----
__device__ __forceinline__ ull pack2(float lo, float hi) {
    ull r;
    asm("mov.b64 %0, {%1, %2};" : "=l"(r) : "f"(lo), "f"(hi));
    return r;
}
__device__ __forceinline__ void fma2(ull &acc, ull a, ull b) {
    asm("fma.rn.f32x2 %0, %1, %2, %0;" : "+l"(acc) : "l"(a), "l"(b));
}
__device__ __forceinline__ float hsum2(ull v) {
    float lo, hi;
    asm("mov.b64 {%0, %1}, %2;" : "=f"(lo), "=f"(hi) : "l"(v));
    return lo + hi;
}

// fast activations: MUFU.RCP instead of IEEE divide
__device__ __forceinline__ float frcp(float x) {
    float r;
    asm("rcp.approx.f32 %0, %1;" : "=f"(r) : "f"(x));
    return r;
}
__device__ __forceinline__ float sigm(float x) { return frcp(1.f + __expf(-x)); }
__device__ __forceinline__ float tanh_f(float x) {
    return fmaf(-2.f, frcp(1.f + __expf(2.f * x)), 1.f);
}

// dual-chain 96x32 matvec: shared weights W[0:16)=r, [16:32)=z, [32:48)=n
__device__ __forceinline__ void matvec3x2(const float* __restrict__ hA, const float* __restrict__ hB,
                                          const ull* W,
                                          float& grA, float& gzA, float& gnA,
                                          float& grB, float& gzB, float& gnB) {
    const ulonglong2* a4 = (const ulonglong2*)hA;
    const ulonglong2* b4 = (const ulonglong2*)hB;
    ull arA = 0, azA = 0, anA = 0, arB = 0, azB = 0, anB = 0;
#pragma unroll
    for (int p = 0; p < 8; p++) {
        ulonglong2 va = a4[p], vb = b4[p];
        fma2(arA, W[2 * p], va.x);      fma2(arA, W[2 * p + 1], va.y);
        fma2(azA, W[16 + 2 * p], va.x); fma2(azA, W[16 + 2 * p + 1], va.y);
        fma2(anA, W[32 + 2 * p], va.x); fma2(anA, W[32 + 2 * p + 1], va.y);
        fma2(arB, W[2 * p], vb.x);      fma2(arB, W[2 * p + 1], vb.y);
        fma2(azB, W[16 + 2 * p], vb.x); fma2(azB, W[16 + 2 * p + 1], vb.y);
        fma2(anB, W[32 + 2 * p], vb.x); fma2(anB, W[32 + 2 * p + 1], vb.y);
    }
    grA = hsum2(arA); gzA = hsum2(azA); gnA = hsum2(anA);
    grB = hsum2(arB); gzB = hsum2(azB); gnB = hsum2(anB);
}

// ---- K1: gating (top-2 softmax) + deterministic same-expert chain pairing ----
__global__ void k_gate(const int* __restrict__ horizon, const float* __restrict__ emb,
                       const float* __restrict__ W_gate, const float* __restrict__ b_gate) {
    __shared__ int sce[NS];
    int b = threadIdx.x;
    const float* ev = emb + (size_t)horizon[b] * ND;
    float l[NE];
#pragma unroll
    for (int e = 0; e < NE; e++) {
        float acc = b_gate[e];
        for (int d = 0; d < ND; d++) acc += W_gate[e * ND + d] * ev[d];
        l[e] = acc;
    }
    int i0 = 0;
#pragma unroll
    for (int e = 1; e < NE; e++) if (l[e] > l[i0]) i0 = e;
    int i1 = -1;
#pragma unroll
    for (int e = 0; e < NE; e++) if (e != i0 && (i1 < 0 || l[e] > l[i1])) i1 = e;
    float ex = __expf(l[i1] - l[i0]);   // l[i0] is the max
    float w0 = 1.f / (1.f + ex);
    g_ce[2 * b] = i0;     g_cw[2 * b] = w0;
    g_ce[2 * b + 1] = i1; g_cw[2 * b + 1] = ex * w0;
    sce[2 * b] = i0; sce[2 * b + 1] = i1;
    __syncthreads();
    if (b == 0) {
        int pend[NE] = {-1, -1, -1, -1};
        int np = 0;
        for (int s = 0; s < NS; s++) {
            int e = sce[s];
            if (pend[e] < 0) pend[e] = s;
            else { g_pairA[np] = pend[e]; g_pairB[np] = s; np++; pend[e] = -1; }
        }
        for (int e = 0; e < NE; e++)
            if (pend[e] >= 0) { g_pairA[np] = pend[e]; g_pairB[np] = pend[e]; np++; }
        g_npair = np;
    }
}

// ---- K2: M[e][g][f] = sum_d Wih0[e][g][d] * W_in[d][f] ----
__global__ void k_M(const float* __restrict__ Wih0, const float* __restrict__ W_in) {
    int e = blockIdx.x, g = blockIdx.y, f = threadIdx.x;
    if (f >= NF) return;
    float acc = 0.f;
    for (int d = 0; d < ND; d++) acc += Wih0[(e * 96 + g) * ND + d] * W_in[d * NF + f];
    g_M[(e * 96 + g) * NF + f] = acc;
}

// ---- K3: chain constants: (b_in + emb[h_b]) . Wih0 + bih0 (+ bhh0 for r,z) ----
__global__ void k_c(const int* __restrict__ horizon, const float* __restrict__ b_in,
                    const float* __restrict__ emb, const float* __restrict__ Wih0,
                    const float* __restrict__ bih0, const float* __restrict__ bhh0) {
    int s = blockIdx.x, g = threadIdx.x;
    int b = s >> 1, e = g_ce[s];
    __shared__ float v[ND];
    if (g < ND) v[g] = b_in[g] + emb[(size_t)horizon[b] * ND + g];
    __syncthreads();
    float acc = bih0[e * 96 + g] + (g < 64 ? bhh0[e * 96 + g] : 0.f);  // bhh0_n stays with r*gh_n
#pragma unroll 8
    for (int d = 0; d < ND; d++) acc += Wih0[(e * 96 + g) * ND + d] * v[d];
    g_c[s * 96 + g] = acc;
}

// ---- K5: FUSED kernel. 1 block = 2 same-expert chains, 6 warps.
// warps 0-2: 3-stage recurrence pipeline (layer0 | Wih1 | layer1), super-steps of RR
// warps 3-5: produce layer-0 input gates x.M^T + c for super-step k+1 into smem ring,
//            and stage raw x rows for super-step k+2 (double-buffered)
__global__ __launch_bounds__(192, 2) void k_fused(
    const float* __restrict__ x,
    const float* __restrict__ Whh0, const float* __restrict__ bhh0,
    const float* __restrict__ Wih1, const float* __restrict__ Whh1,
    const float* __restrict__ bih1, const float* __restrict__ bhh1,
    const float* __restrict__ Wh1,  const float* __restrict__ bh1,
    const float* __restrict__ Wh2,  const float* __restrict__ bh2)
{
    if ((int)blockIdx.x >= g_npair) return;
    int sA = g_pairA[blockIdx.x], sB = g_pairB[blockIdx.x];
    int e = g_ce[sA];
    int bA = sA >> 1, bB = sB >> 1;
    int lane = threadIdx.x & 31;
    int warp = threadIdx.x >> 5;

    __shared__ __align__(16) float h0buf[2][2][RR][32];   // [chain][buf][j][lane]
    __shared__ __align__(16) float xgbuf[2][2][RR][96];   // warp1 -> warp2 feeds
    __shared__ __align__(16) float x0buf[2][2][RR][96];   // xg-warps -> warp0 feeds
    __shared__ __align__(16) float xrow[2][2][RR][52];    // staged raw x rows (padded)
    __shared__ __align__(16) float h1tmp[2][2][32];       // warp2 parity ring

    // wreg overlays: warps 0-2 use [0:48) = Wr|Wz|Wn; warps 3-5 use [0:26) = M row
    ull wreg[48];
    float cr = 0.f, cz = 0.f, cn = 0.f, cA = 0.f, cB = 0.f;

    if (warp < 3) {
        const float* Wbase = (warp == 0) ? (Whh0 + e * 96 * NH)
                           : (warp == 1) ? (Wih1 + e * 96 * NH)
                                         : (Whh1 + e * 96 * NH);
#pragma unroll
        for (int p = 0; p < 16; p++) {
            wreg[p]      = pack2(Wbase[lane * NH + 2 * p],        Wbase[lane * NH + 2 * p + 1]);
            wreg[16 + p] = pack2(Wbase[(32 + lane) * NH + 2 * p], Wbase[(32 + lane) * NH + 2 * p + 1]);
            wreg[32 + p] = pack2(Wbase[(64 + lane) * NH + 2 * p], Wbase[(64 + lane) * NH + 2 * p + 1]);
        }
        if (warp == 0) {
            cn = bhh0[e * 96 + 64 + lane];                      // bhh0_n (inside r*(.))
        } else if (warp == 1) {
            cr = bih1[e * 96 + lane]      + bhh1[e * 96 + lane];
            cz = bih1[e * 96 + 32 + lane] + bhh1[e * 96 + 32 + lane];
            cn = bih1[e * 96 + 64 + lane];
        } else {
            cn = bhh1[e * 96 + 64 + lane];                      // bhh1_n (inside r*(.))
        }
    } else {
        int g = (warp - 3) * 32 + lane;
        const float* mrow = g_M + (e * 96 + g) * NF;
#pragma unroll
        for (int p = 0; p < 25; p++) wreg[p] = pack2(mrow[2 * p], mrow[2 * p + 1]);
        wreg[25] = 0ULL;                 // pairs with xrow pad floats 50,51
        cA = g_c[sA * 96 + g];
        cB = g_c[sB * 96 + g];
    }

    // init ring entry points + xrow pads
    if (threadIdx.x < 32) {
        h0buf[0][1][RR - 1][lane] = 0.f;   // read by warp0 at k=0, j=0
        h0buf[1][1][RR - 1][lane] = 0.f;
        h1tmp[0][1][lane] = 0.f;           // read by warp2 at t=0 (parity 1)
        h1tmp[1][1][lane] = 0.f;
    }
    if (threadIdx.x >= 32 && threadIdx.x < 32 + 2 * 2 * RR) {
        int q = threadIdx.x - 32;
        int c = q >> 3, bf = (q >> 2) & 1, j = q & 3;
        xrow[c][bf][j][50] = 0.f; xrow[c][bf][j][51] = 0.f;
    }
    // prologue: stage x rows for super-steps 0 and 1 (all 6 warps cooperate)
    for (int idx = threadIdx.x; idx < 2 * 2 * RR * NF; idx += 192) {
        int bf = idx / (2 * RR * NF);
        int rem = idx % (2 * RR * NF);
        int c = rem / (RR * NF);
        int r2 = rem % (RR * NF);
        int j = r2 / NF, f = r2 % NF;
        int bb = c ? bB : bA;
        xrow[c][bf][j][f] = x[((size_t)bb * NL + bf * RR + j) * NF + f];
    }
    __syncthreads();
    // prologue: compute x0buf for k=0 from xrow buf0
    if (warp >= 3) {
        int g = (warp - 3) * 32 + lane;
#pragma unroll
        for (int j = 0; j < RR; j++) {
            const ulonglong2* xa = (const ulonglong2*)&xrow[0][0][j][0];
            const ulonglong2* xb = (const ulonglong2*)&xrow[1][0][j][0];
            ull a0 = 0, a1 = 0, b0 = 0, b1 = 0;
#pragma unroll
            for (int q = 0; q < 13; q++) {
                ulonglong2 va = xa[q], vb = xb[q];
                fma2(a0, wreg[2 * q], va.x); fma2(a1, wreg[2 * q + 1], va.y);
                fma2(b0, wreg[2 * q], vb.x); fma2(b1, wreg[2 * q + 1], vb.y);
            }
            x0buf[0][0][j][g] = hsum2(a0) + hsum2(a1) + cA;
            x0buf[1][0][j][g] = hsum2(b0) + hsum2(b1) + cB;
        }
    }
    __syncthreads();

    float hA = 0.f, hB = 0.f;   // warp0: h0; warp2: h1

    for (int k = 0; k <= NK + 1; k++) {
        int buf = k & 1;
        if (warp == 0) {
            if (k < NK) {
#pragma unroll
                for (int j = 0; j < RR; j++) {
                    // issue feed loads first so their latency hides under the matvec
                    float xrA = x0buf[0][buf][j][lane];
                    float xzA = x0buf[0][buf][j][32 + lane];
                    float xnA = x0buf[0][buf][j][64 + lane];
                    float xrB = x0buf[1][buf][j][lane];
                    float xzB = x0buf[1][buf][j][32 + lane];
                    float xnB = x0buf[1][buf][j][64 + lane];
                    const float* hA2 = (j == 0) ? &h0buf[0][buf ^ 1][RR - 1][0] : &h0buf[0][buf][j - 1][0];
                    const float* hB2 = (j == 0) ? &h0buf[1][buf ^ 1][RR - 1][0] : &h0buf[1][buf][j - 1][0];
                    float grA, gzA, gnA, grB, gzB, gnB;
                    matvec3x2(hA2, hB2, wreg, grA, gzA, gnA, grB, gzB, gnB);
                    float rA = sigm(xrA + grA);
                    float zA = sigm(xzA + gzA);
                    float nA = tanh_f(xnA + rA * (gnA + cn));
                    hA = (1.f - zA) * nA + zA * hA;
                    float rB = sigm(xrB + grB);
                    float zB = sigm(xzB + gzB);
                    float nB = tanh_f(xnB + rB * (gnB + cn));
                    hB = (1.f - zB) * nB + zB * hB;
                    h0buf[0][buf][j][lane] = hA;
                    h0buf[1][buf][j][lane] = hB;
                    __syncwarp();
                }
            }
        } else if (warp == 1) {
            if (k >= 1 && k <= NK) {
                int kb = buf ^ 1;   // (k-1)&1
#pragma unroll
                for (int j = 0; j < RR; j++) {
                    float grA, gzA, gnA, grB, gzB, gnB;
                    matvec3x2(&h0buf[0][kb][j][0], &h0buf[1][kb][j][0],
                              wreg, grA, gzA, gnA, grB, gzB, gnB);
                    xgbuf[0][kb][j][lane]      = grA + cr;
                    xgbuf[0][kb][j][32 + lane] = gzA + cz;
                    xgbuf[0][kb][j][64 + lane] = gnA + cn;
                    xgbuf[1][kb][j][lane]      = grB + cr;
                    xgbuf[1][kb][j][32 + lane] = gzB + cz;
                    xgbuf[1][kb][j][64 + lane] = gnB + cn;
                }
            }
        } else if (warp == 2) {
            if (k >= 2) {
                int kb = buf;       // (k-2)&1
#pragma unroll
                for (int j = 0; j < RR; j++) {
                    float frA = xgbuf[0][kb][j][lane];
                    float fzA = xgbuf[0][kb][j][32 + lane];
                    float fnA = xgbuf[0][kb][j][64 + lane];
                    float frB = xgbuf[1][kb][j][lane];
                    float fzB = xgbuf[1][kb][j][32 + lane];
                    float fnB = xgbuf[1][kb][j][64 + lane];
                    float grA, gzA, gnA, grB, gzB, gnB;
                    matvec3x2(&h1tmp[0][(j & 1) ^ 1][0], &h1tmp[1][(j & 1) ^ 1][0],
                              wreg, grA, gzA, gnA, grB, gzB, gnB);
                    float rA = sigm(frA + grA);
                    float zA = sigm(fzA + gzA);
                    float nA = tanh_f(fnA + rA * (gnA + cn));
                    hA = (1.f - zA) * nA + zA * hA;
                    float rB = sigm(frB + grB);
                    float zB = sigm(fzB + gzB);
                    float nB = tanh_f(fnB + rB * (gnB + cn));
                    hB = (1.f - zB) * nB + zB * hB;
                    h1tmp[0][j & 1][lane] = hA;
                    h1tmp[1][j & 1][lane] = hB;
                    __syncwarp();
                }
            }
        } else {
            // producer warps: stage x rows for k+2 into xrow[.][buf], then
            // compute x0buf feeds for k+1 from xrow[.][buf^1] (filled at k-1)
            if (k + 2 < NK) {
                int l96 = threadIdx.x - 96;
                for (int idx = l96; idx < 2 * RR * NF; idx += 96) {
                    int c = idx / (RR * NF);
                    int r2 = idx % (RR * NF);
                    int j = r2 / NF, f = r2 % NF;
                    int bb = c ? bB : bA;
                    xrow[c][buf][j][f] = x[((size_t)bb * NL + (size_t)(k + 2) * RR + j) * NF + f];
                }
            }
            if (k + 1 < NK) {
                int g = (warp - 3) * 32 + lane;
                int nb = buf ^ 1;   // (k+1)&1
#pragma unroll
                for (int j = 0; j < RR; j++) {
                    const ulonglong2* xa = (const ulonglong2*)&xrow[0][nb][j][0];
                    const ulonglong2* xb = (const ulonglong2*)&xrow[1][nb][j][0];
                    ull a0 = 0, a1 = 0, b0 = 0, b1 = 0;
#pragma unroll
                    for (int q = 0; q < 13; q++) {
                        ulonglong2 va = xa[q], vb = xb[q];
                        fma2(a0, wreg[2 * q], va.x); fma2(a1, wreg[2 * q + 1], va.y);
                        fma2(b0, wreg[2 * q], vb.x); fma2(b1, wreg[2 * q + 1], vb.y);
                    }
                    x0buf[0][nb][j][g] = hsum2(a0) + hsum2(a1) + cA;
                    x0buf[1][nb][j][g] = hsum2(b0) + hsum2(b1) + cB;
                }
            }
        }
        __syncthreads();
    }

    // final h1 per chain in h1tmp[c][1] (t=1799 has parity 1); last barrier published it
    if (warp < 2) {
        int s = warp ? sB : sA;
        const float* h1 = &h1tmp[warp][1][0];
        float acc = bh1[e * 32 + lane];
#pragma unroll
        for (int j = 0; j < NH; j++) acc += Wh1[(e * 32 + lane) * NH + j] * h1[j];
        float hid = fmaxf(acc, 0.f);
        float v = Wh2[e * 32 + lane] * hid;
#pragma unroll
        for (int off = 16; off > 0; off >>= 1) v += __shfl_down_sync(0xffffffffu, v, off);
        if (lane == 0) g_predw[s] = g_cw[s] * (v + bh2[e]);
    }
}

// ---- K6: combine the two routed chains per batch ----
__global__ void k_final(float* __restrict__ out) {
    int b = threadIdx.x;
    out[b] = g_predw[2 * b] + g_predw[2 * b + 1];
}

extern "C" void kernel_launch(void* const* d_in, const int* in_sizes, int n_in,
                              void* d_out, int out_size) {
    const float* x       = (const float*)d_in[0];
    const int*   horizon = (const int*)  d_in[1];
    const float* W_in    = (const float*)d_in[2];
    const float* b_in    = (const float*)d_in[3];
    const float* emb     = (const float*)d_in[4];
    const float* W_gate  = (const float*)d_in[5];
    const float* b_gate  = (const float*)d_in[6];
    const float* Wih0    = (const float*)d_in[7];
    const float* Whh0    = (const float*)d_in[8];
    const float* bih0    = (const float*)d_in[9];
    const float* bhh0    = (const float*)d_in[10];
    const float* Wih1    = (const float*)d_in[11];
    const float* Whh1    = (const float*)d_in[12];
    const float* bih1    = (const float*)d_in[13];
    const float* bhh1    = (const float*)d_in[14];
    const float* Wh1     = (const float*)d_in[15];
    const float* bh1     = (const float*)d_in[16];
    const float* Wh2     = (const float*)d_in[17];
    const float* bh2     = (const float*)d_in[18];
    float* out = (float*)d_out;

    k_gate<<<1, NB>>>(horizon, emb, W_gate, b_gate);
    k_M<<<dim3(NE, 96), 64>>>(Wih0, W_in);
    k_c<<<NS, 96>>>(horizon, b_in, emb, Wih0, bih0, bhh0);
    k_fused<<<MAXP, 192>>>(x, Whh0, bhh0, Wih1, Whh1, bih1, bhh1, Wh1, bh1, Wh2, bh2);
    k_final<<<1, NB>>>(out);
}

// round 10
// speedup vs baseline: 1.2350x; 1.2350x over previous
#include <cuda_runtime.h>
#include <cstdint>

// MoEGRU: B=256, L=1800, F=50, E=4, K=2, H=32, D=64, HU=32
#define NB 256
#define NL 1800
#define NF 50
#define NE 4
#define NH 32
#define ND 64
#define NS 512       // routed chains = B*K
#define TT 40        // time-tile for xg0 GEMM
#define NTILE 45     // 1800/40
#define RR 4         // recurrence pipeline batch (even, divides NL)
#define NK (NL / RR) // 450 super-steps
#define MAXP 260     // max chain pairs (512/2 + up to 4 odd-bucket pads)

typedef unsigned long long ull;

// ---- scratch (static device globals; no allocation allowed) ----
__device__ float g_xg0[(size_t)NS * NL * 96];   // precomputed input gates, layer 0
__device__ float g_Mt[NE * 25 * 96 * 2];        // fused W_in->Wih0, transposed+pair-packed:
                                                // [e][p][row][2] so row-major LDG is coalesced
__device__ float g_c[NS * 96];                  // per-chain constant (emb/bias folded)
__device__ int   g_ce[NS];                      // chain -> expert
__device__ float g_cw[NS];                      // chain -> routing weight
__device__ float g_predw[NS];                   // weighted per-chain prediction
__device__ int   g_pairA[MAXP], g_pairB[MAXP];  // same-expert chain pairs
__device__ int   g_npair;

// ---- packed f32x2 helpers (sm_103a dual-fp32 pipe) ----
__device__ __forceinline__ ull pack2(float lo, float hi) {
    ull r;
    asm("mov.b64 %0, {%1, %2};" : "=l"(r) : "f"(lo), "f"(hi));
    return r;
}
__device__ __forceinline__ void fma2(ull &acc, ull a, ull b) {
    asm("fma.rn.f32x2 %0, %1, %2, %0;" : "+l"(acc) : "l"(a), "l"(b));
}
__device__ __forceinline__ float hsum2(ull v) {
    float lo, hi;
    asm("mov.b64 {%0, %1}, %2;" : "=f"(lo), "=f"(hi) : "l"(v));
    return lo + hi;
}

// fast activations: MUFU.RCP instead of IEEE divide
__device__ __forceinline__ float frcp(float x) {
    float r;
    asm("rcp.approx.f32 %0, %1;" : "=f"(r) : "f"(x));
    return r;
}
__device__ __forceinline__ float sigm(float x) { return frcp(1.f + __expf(-x)); }
__device__ __forceinline__ float tanh_f(float x) {
    return fmaf(-2.f, frcp(1.f + __expf(2.f * x)), 1.f);
}

// dual-chain 96x32 matvec: shared weights W[0:16)=r, [16:32)=z, [32:48)=n
__device__ __forceinline__ void matvec3x2(const float* __restrict__ hA, const float* __restrict__ hB,
                                          const ull* W,
                                          float& grA, float& gzA, float& gnA,
                                          float& grB, float& gzB, float& gnB) {
    const ulonglong2* a4 = (const ulonglong2*)hA;
    const ulonglong2* b4 = (const ulonglong2*)hB;
    ull arA = 0, azA = 0, anA = 0, arB = 0, azB = 0, anB = 0;
#pragma unroll
    for (int p = 0; p < 8; p++) {
        ulonglong2 va = a4[p], vb = b4[p];
        fma2(arA, W[2 * p], va.x);      fma2(arA, W[2 * p + 1], va.y);
        fma2(azA, W[16 + 2 * p], va.x); fma2(azA, W[16 + 2 * p + 1], va.y);
        fma2(anA, W[32 + 2 * p], va.x); fma2(anA, W[32 + 2 * p + 1], va.y);
        fma2(arB, W[2 * p], vb.x);      fma2(arB, W[2 * p + 1], vb.y);
        fma2(azB, W[16 + 2 * p], vb.x); fma2(azB, W[16 + 2 * p + 1], vb.y);
        fma2(anB, W[32 + 2 * p], vb.x); fma2(anB, W[32 + 2 * p + 1], vb.y);
    }
    grA = hsum2(arA); gzA = hsum2(azA); gnA = hsum2(anA);
    grB = hsum2(arB); gzB = hsum2(azB); gnB = hsum2(anB);
}

// ---- K1: gating (top-2 softmax) + deterministic same-expert chain pairing ----
__global__ void k_gate(const int* __restrict__ horizon, const float* __restrict__ emb,
                       const float* __restrict__ W_gate, const float* __restrict__ b_gate) {
    __shared__ int sce[NS];
    int b = threadIdx.x;
    const float* ev = emb + (size_t)horizon[b] * ND;
    float l[NE];
#pragma unroll
    for (int e = 0; e < NE; e++) {
        float acc = b_gate[e];
        for (int d = 0; d < ND; d++) acc += W_gate[e * ND + d] * ev[d];
        l[e] = acc;
    }
    int i0 = 0;
#pragma unroll
    for (int e = 1; e < NE; e++) if (l[e] > l[i0]) i0 = e;
    int i1 = -1;
#pragma unroll
    for (int e = 0; e < NE; e++) if (e != i0 && (i1 < 0 || l[e] > l[i1])) i1 = e;
    float ex = __expf(l[i1] - l[i0]);   // l[i0] is the max
    float w0 = 1.f / (1.f + ex);
    g_ce[2 * b] = i0;     g_cw[2 * b] = w0;
    g_ce[2 * b + 1] = i1; g_cw[2 * b + 1] = ex * w0;
    sce[2 * b] = i0; sce[2 * b + 1] = i1;
    __syncthreads();
    if (b == 0) {
        int pend[NE] = {-1, -1, -1, -1};
        int np = 0;
        for (int s = 0; s < NS; s++) {
            int e = sce[s];
            if (pend[e] < 0) pend[e] = s;
            else { g_pairA[np] = pend[e]; g_pairB[np] = s; np++; pend[e] = -1; }
        }
        for (int e = 0; e < NE; e++)
            if (pend[e] >= 0) { g_pairA[np] = pend[e]; g_pairB[np] = pend[e]; np++; }
        g_npair = np;
    }
}

// ---- K2: Mt[e][f/2][g][f&1] = sum_d Wih0[e][g][d] * W_in[d][f]  (transposed layout) ----
__global__ void k_M(const float* __restrict__ Wih0, const float* __restrict__ W_in) {
    int e = blockIdx.x, g = blockIdx.y, f = threadIdx.x;
    if (f >= NF) return;
    float acc = 0.f;
    for (int d = 0; d < ND; d++) acc += Wih0[(e * 96 + g) * ND + d] * W_in[d * NF + f];
    g_Mt[((e * 25 + (f >> 1)) * 96 + g) * 2 + (f & 1)] = acc;
}

// ---- K3: chain constants: (b_in + emb[h_b]) . Wih0 + bih0 (+ bhh0 for r,z) ----
__global__ void k_c(const int* __restrict__ horizon, const float* __restrict__ b_in,
                    const float* __restrict__ emb, const float* __restrict__ Wih0,
                    const float* __restrict__ bih0, const float* __restrict__ bhh0) {
    int s = blockIdx.x, g = threadIdx.x;
    int b = s >> 1, e = g_ce[s];
    __shared__ float v[ND];
    if (g < ND) v[g] = b_in[g] + emb[(size_t)horizon[b] * ND + g];
    __syncthreads();
    float acc = bih0[e * 96 + g] + (g < 64 ? bhh0[e * 96 + g] : 0.f);  // bhh0_n stays with r*gh_n
#pragma unroll 8
    for (int d = 0; d < ND; d++) acc += Wih0[(e * 96 + g) * ND + d] * v[d];
    g_c[s * 96 + g] = acc;
}

// ---- K4: xg0 for BOTH chains of batch b in one block (shared x, coalesced Mt loads) ----
__global__ __launch_bounds__(96, 4) void k_xg0(const float* __restrict__ x) {
    int b = blockIdx.x, tile = blockIdx.y;
    int t0 = tile * TT;
    int tid = threadIdx.x;
    int e0 = g_ce[2 * b], e1 = g_ce[2 * b + 1];
    __shared__ __align__(16) float xs[TT * 52];   // 52-float row stride (16B-aligned rows)
    const float* xsrc = x + ((size_t)b * NL + t0) * NF;
    for (int idx = tid; idx < TT * NF; idx += 96)
        xs[(idx / NF) * 52 + (idx % NF)] = xsrc[idx];
    for (int r = tid; r < TT; r += 96) { xs[r * 52 + 50] = 0.f; xs[r * 52 + 51] = 0.f; }

    // coalesced: consecutive threads read consecutive float2 pairs
    const ull* Mt = (const ull*)g_Mt;
    ull ma[26], mb[26];
#pragma unroll
    for (int p = 0; p < 25; p++) {
        ma[p] = Mt[(e0 * 25 + p) * 96 + tid];
        mb[p] = Mt[(e1 * 25 + p) * 96 + tid];
    }
    ma[25] = 0ULL; mb[25] = 0ULL;   // pairs x pad (zeroed) contribute 0
    float ca = g_c[(2 * b) * 96 + tid];
    float cb = g_c[(2 * b + 1) * 96 + tid];
    __syncthreads();

    float* da = g_xg0 + ((size_t)(2 * b) * NL + t0) * 96 + tid;
    float* db = g_xg0 + ((size_t)(2 * b + 1) * NL + t0) * 96 + tid;
    for (int tt = 0; tt < TT; tt++) {
        const ulonglong2* x4 = (const ulonglong2*)(xs + tt * 52);
        ull a0 = 0, a1 = 0, a2 = 0, a3 = 0, b0 = 0, b1 = 0, b2 = 0, b3 = 0;
#pragma unroll
        for (int q = 0; q < 13; q++) {
            ulonglong2 v = x4[q];
            if (q & 1) {
                fma2(a2, ma[2 * q], v.x); fma2(a3, ma[2 * q + 1], v.y);
                fma2(b2, mb[2 * q], v.x); fma2(b3, mb[2 * q + 1], v.y);
            } else {
                fma2(a0, ma[2 * q], v.x); fma2(a1, ma[2 * q + 1], v.y);
                fma2(b0, mb[2 * q], v.x); fma2(b1, mb[2 * q + 1], v.y);
            }
        }
        da[(size_t)tt * 96] = (hsum2(a0) + hsum2(a1)) + (hsum2(a2) + hsum2(a3)) + ca;
        db[(size_t)tt * 96] = (hsum2(b0) + hsum2(b1)) + (hsum2(b2) + hsum2(b3)) + cb;
    }
}

// ---- K5: recurrent kernel. 1 block = 2 same-expert chains, FOUR warps with role
// rotation so co-resident blocks spread stages over all 4 SMSPs:
//   role 0: layer-0 cell for super-step k      -> h0buf[c][k&1]
//   role 1: Wih1 . h0 for super-step k-1       -> xgbuf[c][(k-1)&1]
//   role 2: layer-1 cell for super-step k-2
//   role 3: FEED: stream g_xg0 feeds for k+1 into x0buf[c][(k+1)&1]
__global__ __launch_bounds__(128, 2) void k_rec(
    const float* __restrict__ Whh0, const float* __restrict__ bhh0,
    const float* __restrict__ Wih1, const float* __restrict__ Whh1,
    const float* __restrict__ bih1, const float* __restrict__ bhh1,
    const float* __restrict__ Wh1,  const float* __restrict__ bh1,
    const float* __restrict__ Wh2,  const float* __restrict__ bh2)
{
    if ((int)blockIdx.x >= g_npair) return;
    int sA = g_pairA[blockIdx.x], sB = g_pairB[blockIdx.x];
    int e = g_ce[sA];
    int lane = threadIdx.x & 31;
    int warp = threadIdx.x >> 5;
    // role rotation; the (bid>>7) term de-aliases co-resident blocks (delta bid = 148 = 0 mod 4)
    int role = (warp + blockIdx.x + (blockIdx.x >> 7)) & 3;

    __shared__ __align__(16) float h0buf[2][2][RR][32];   // [chain][buf][j][lane]
    __shared__ __align__(16) float xgbuf[2][2][RR][96];   // role1 -> role2 feeds
    __shared__ __align__(16) float x0buf[2][2][RR][96];   // role3 -> role0 feeds
    __shared__ __align__(16) float h1tmp[2][2][32];       // role2 parity ring

    ull wreg[48];
    float cr = 0.f, cz = 0.f, cn = 0.f;
    if (role < 3) {
        const float* Wbase = (role == 0) ? (Whh0 + e * 96 * NH)
                           : (role == 1) ? (Wih1 + e * 96 * NH)
                                         : (Whh1 + e * 96 * NH);
#pragma unroll
        for (int p = 0; p < 16; p++) {
            wreg[p]      = pack2(Wbase[lane * NH + 2 * p],        Wbase[lane * NH + 2 * p + 1]);
            wreg[16 + p] = pack2(Wbase[(32 + lane) * NH + 2 * p], Wbase[(32 + lane) * NH + 2 * p + 1]);
            wreg[32 + p] = pack2(Wbase[(64 + lane) * NH + 2 * p], Wbase[(64 + lane) * NH + 2 * p + 1]);
        }
        if (role == 0) {
            cn = bhh0[e * 96 + 64 + lane];                      // bhh0_n (inside r*(.))
        } else if (role == 1) {
            cr = bih1[e * 96 + lane]      + bhh1[e * 96 + lane];
            cz = bih1[e * 96 + 32 + lane] + bhh1[e * 96 + 32 + lane];
            cn = bih1[e * 96 + 64 + lane];
        } else {
            cn = bhh1[e * 96 + 64 + lane];                      // bhh1_n (inside r*(.))
        }
    }

    // init ring entry points
    if (threadIdx.x < 32) {
        h0buf[0][1][RR - 1][lane] = 0.f;   // read by role0 at k=0, j=0
        h0buf[1][1][RR - 1][lane] = 0.f;
        h1tmp[0][1][lane] = 0.f;           // read by role2 at t=0 (parity 1)
        h1tmp[1][1][lane] = 0.f;
    }
    __syncthreads();

    const float* xgA = g_xg0 + (size_t)sA * NL * 96;
    const float* xgB = g_xg0 + (size_t)sB * NL * 96;

    // FEED prologue: fill x0buf[.][0] for k=0
    if (role == 3) {
#pragma unroll
        for (int j = 0; j < RR; j++) {
            const float* pA = xgA + (size_t)j * 96;
            const float* pB = xgB + (size_t)j * 96;
            x0buf[0][0][j][lane]      = pA[lane];
            x0buf[0][0][j][32 + lane] = pA[32 + lane];
            x0buf[0][0][j][64 + lane] = pA[64 + lane];
            x0buf[1][0][j][lane]      = pB[lane];
            x0buf[1][0][j][32 + lane] = pB[32 + lane];
            x0buf[1][0][j][64 + lane] = pB[64 + lane];
        }
    }
    __syncthreads();

    float hA = 0.f, hB = 0.f;   // role0: h0; role2: h1

    for (int k = 0; k <= NK + 1; k++) {
        int buf = k & 1;
        if (role == 0) {
            if (k < NK) {
#pragma unroll
                for (int j = 0; j < RR; j++) {
                    // feed loads issue first; latency hides under the matvec
                    float xrA = x0buf[0][buf][j][lane];
                    float xzA = x0buf[0][buf][j][32 + lane];
                    float xnA = x0buf[0][buf][j][64 + lane];
                    float xrB = x0buf[1][buf][j][lane];
                    float xzB = x0buf[1][buf][j][32 + lane];
                    float xnB = x0buf[1][buf][j][64 + lane];
                    const float* hA2 = (j == 0) ? &h0buf[0][buf ^ 1][RR - 1][0] : &h0buf[0][buf][j - 1][0];
                    const float* hB2 = (j == 0) ? &h0buf[1][buf ^ 1][RR - 1][0] : &h0buf[1][buf][j - 1][0];
                    float grA, gzA, gnA, grB, gzB, gnB;
                    matvec3x2(hA2, hB2, wreg, grA, gzA, gnA, grB, gzB, gnB);
                    float rA = sigm(xrA + grA);
                    float zA = sigm(xzA + gzA);
                    float nA = tanh_f(xnA + rA * (gnA + cn));
                    hA = (1.f - zA) * nA + zA * hA;
                    float rB = sigm(xrB + grB);
                    float zB = sigm(xzB + gzB);
                    float nB = tanh_f(xnB + rB * (gnB + cn));
                    hB = (1.f - zB) * nB + zB * hB;
                    h0buf[0][buf][j][lane] = hA;
                    h0buf[1][buf][j][lane] = hB;
                    __syncwarp();
                }
            }
        } else if (role == 1) {
            if (k >= 1 && k <= NK) {
                int kb = buf ^ 1;   // (k-1)&1
#pragma unroll
                for (int j = 0; j < RR; j++) {
                    float grA, gzA, gnA, grB, gzB, gnB;
                    matvec3x2(&h0buf[0][kb][j][0], &h0buf[1][kb][j][0],
                              wreg, grA, gzA, gnA, grB, gzB, gnB);
                    xgbuf[0][kb][j][lane]      = grA + cr;
                    xgbuf[0][kb][j][32 + lane] = gzA + cz;
                    xgbuf[0][kb][j][64 + lane] = gnA + cn;
                    xgbuf[1][kb][j][lane]      = grB + cr;
                    xgbuf[1][kb][j][32 + lane] = gzB + cz;
                    xgbuf[1][kb][j][64 + lane] = gnB + cn;
                }
            }
        } else if (role == 2) {
            if (k >= 2) {
                int kb = buf;       // (k-2)&1
#pragma unroll
                for (int j = 0; j < RR; j++) {
                    float frA = xgbuf[0][kb][j][lane];
                    float fzA = xgbuf[0][kb][j][32 + lane];
                    float fnA = xgbuf[0][kb][j][64 + lane];
                    float frB = xgbuf[1][kb][j][lane];
                    float fzB = xgbuf[1][kb][j][32 + lane];
                    float fnB = xgbuf[1][kb][j][64 + lane];
                    float grA, gzA, gnA, grB, gzB, gnB;
                    matvec3x2(&h1tmp[0][(j & 1) ^ 1][0], &h1tmp[1][(j & 1) ^ 1][0],
                              wreg, grA, gzA, gnA, grB, gzB, gnB);
                    float rA = sigm(frA + grA);
                    float zA = sigm(fzA + gzA);
                    float nA = tanh_f(fnA + rA * (gnA + cn));
                    hA = (1.f - zA) * nA + zA * hA;
                    float rB = sigm(frB + grB);
                    float zB = sigm(fzB + gzB);
                    float nB = tanh_f(fnB + rB * (gnB + cn));
                    hB = (1.f - zB) * nB + zB * hB;
                    h1tmp[0][j & 1][lane] = hA;
                    h1tmp[1][j & 1][lane] = hB;
                    __syncwarp();
                }
            }
        } else {
            // FEED: stream g_xg0 for super-step k+1 into x0buf[.][buf^1]
            if (k + 1 < NK) {
                int nb = buf ^ 1;
#pragma unroll
                for (int j = 0; j < RR; j++) {
                    size_t t = (size_t)(k + 1) * RR + j;
                    const float* pA = xgA + t * 96;
                    const float* pB = xgB + t * 96;
                    x0buf[0][nb][j][lane]      = pA[lane];
                    x0buf[0][nb][j][32 + lane] = pA[32 + lane];
                    x0buf[0][nb][j][64 + lane] = pA[64 + lane];
                    x0buf[1][nb][j][lane]      = pB[lane];
                    x0buf[1][nb][j][32 + lane] = pB[32 + lane];
                    x0buf[1][nb][j][64 + lane] = pB[64 + lane];
                }
            }
        }
        __syncthreads();
    }

    // final h1 per chain in h1tmp[c][1] (t=1799 has parity 1); last barrier published it
    if (warp < 2) {
        int s = warp ? sB : sA;
        const float* h1 = &h1tmp[warp][1][0];
        float acc = bh1[e * 32 + lane];
#pragma unroll
        for (int j = 0; j < NH; j++) acc += Wh1[(e * 32 + lane) * NH + j] * h1[j];
        float hid = fmaxf(acc, 0.f);
        float v = Wh2[e * 32 + lane] * hid;
#pragma unroll
        for (int off = 16; off > 0; off >>= 1) v += __shfl_down_sync(0xffffffffu, v, off);
        if (lane == 0) g_predw[s] = g_cw[s] * (v + bh2[e]);
    }
}

// ---- K6: combine the two routed chains per batch ----
__global__ void k_final(float* __restrict__ out) {
    int b = threadIdx.x;
    out[b] = g_predw[2 * b] + g_predw[2 * b + 1];
}

extern "C" void kernel_launch(void* const* d_in, const int* in_sizes, int n_in,
                              void* d_out, int out_size) {
    const float* x       = (const float*)d_in[0];
    const int*   horizon = (const int*)  d_in[1];
    const float* W_in    = (const float*)d_in[2];
    const float* b_in    = (const float*)d_in[3];
    const float* emb     = (const float*)d_in[4];
    const float* W_gate  = (const float*)d_in[5];
    const float* b_gate  = (const float*)d_in[6];
    const float* Wih0    = (const float*)d_in[7];
    const float* Whh0    = (const float*)d_in[8];
    const float* bih0    = (const float*)d_in[9];
    const float* bhh0    = (const float*)d_in[10];
    const float* Wih1    = (const float*)d_in[11];
    const float* Whh1    = (const float*)d_in[12];
    const float* bih1    = (const float*)d_in[13];
    const float* bhh1    = (const float*)d_in[14];
    const float* Wh1     = (const float*)d_in[15];
    const float* bh1     = (const float*)d_in[16];
    const float* Wh2     = (const float*)d_in[17];
    const float* bh2     = (const float*)d_in[18];
    float* out = (float*)d_out;

    k_gate<<<1, NB>>>(horizon, emb, W_gate, b_gate);
    k_M<<<dim3(NE, 96), 64>>>(Wih0, W_in);
    k_c<<<NS, 96>>>(horizon, b_in, emb, Wih0, bih0, bhh0);
    k_xg0<<<dim3(NB, NTILE), 96>>>(x);
    k_rec<<<MAXP, 128>>>(Whh0, bhh0, Wih1, Whh1, bih1, bhh1, Wh1, bh1, Wh2, bh2);
    k_final<<<1, NB>>>(out);
}

// round 14
// speedup vs baseline: 1.2816x; 1.0377x over previous
#include <cuda_runtime.h>
#include <cstdint>

// MoEGRU: B=256, L=1800, F=50, E=4, K=2, H=32, D=64, HU=32
#define NB 256
#define NL 1800
#define NF 50
#define NE 4
#define NH 32
#define ND 64
#define NS 512       // routed chains = B*K
#define TT 40        // time-tile for xg0 GEMM
#define NTILE 45     // 1800/40
#define RR 4         // recurrence pipeline batch (even, divides NL)
#define NK (NL / RR) // 450 super-steps

typedef unsigned long long ull;

// ---- scratch (static device globals; no allocation allowed) ----
__device__ float g_xg0[(size_t)NS * NL * 96];   // precomputed input gates, layer 0
__device__ float g_Mt[NE * 25 * 96 * 2];        // fused W_in->Wih0, transposed+pair-packed
__device__ float g_c[NS * 96];                  // per-chain constant (emb/bias folded)
__device__ int   g_ce[NS];                      // chain -> expert
__device__ float g_cw[NS];                      // chain -> routing weight
__device__ float g_predw[NS];                   // weighted per-chain prediction

// ---- packed f32x2 helpers (sm_103a dual-fp32 pipe) ----
__device__ __forceinline__ ull pack2(float lo, float hi) {
    ull r;
    asm("mov.b64 %0, {%1, %2};" : "=l"(r) : "f"(lo), "f"(hi));
    return r;
}
__device__ __forceinline__ void fma2(ull &acc, ull a, ull b) {
    asm("fma.rn.f32x2 %0, %1, %2, %0;" : "+l"(acc) : "l"(a), "l"(b));
}
__device__ __forceinline__ float hsum2(ull v) {
    float lo, hi;
    asm("mov.b64 {%0, %1}, %2;" : "=f"(lo), "=f"(hi) : "l"(v));
    return lo + hi;
}

// fast activations: MUFU.RCP instead of IEEE divide
__device__ __forceinline__ float frcp(float x) {
    float r;
    asm("rcp.approx.f32 %0, %1;" : "=f"(r) : "f"(x));
    return r;
}
__device__ __forceinline__ float sigm(float x) { return frcp(1.f + __expf(-x)); }
__device__ __forceinline__ float tanh_f(float x) {
    return fmaf(-2.f, frcp(1.f + __expf(2.f * x)), 1.f);
}

// single-chain 96x32 matvec: weights W[0:16)=r, [16:32)=z, [32:48)=n
__device__ __forceinline__ void matvec3(const float* __restrict__ h,
                                        const ull* W,
                                        float& gr, float& gz, float& gn) {
    const ulonglong2* h4 = (const ulonglong2*)h;
    ull ar = 0, az = 0, an = 0;
#pragma unroll
    for (int p = 0; p < 8; p++) {
        ulonglong2 v = h4[p];
        fma2(ar, W[2 * p], v.x);      fma2(ar, W[2 * p + 1], v.y);
        fma2(az, W[16 + 2 * p], v.x); fma2(az, W[16 + 2 * p + 1], v.y);
        fma2(an, W[32 + 2 * p], v.x); fma2(an, W[32 + 2 * p + 1], v.y);
    }
    gr = hsum2(ar); gz = hsum2(az); gn = hsum2(an);
}

// ---- K1: gating (top-2 softmax) ----
__global__ void k_gate(const int* __restrict__ horizon, const float* __restrict__ emb,
                       const float* __restrict__ W_gate, const float* __restrict__ b_gate) {
    int b = threadIdx.x;
    const float* ev = emb + (size_t)horizon[b] * ND;
    float l[NE];
#pragma unroll
    for (int e = 0; e < NE; e++) {
        float acc = b_gate[e];
        for (int d = 0; d < ND; d++) acc += W_gate[e * ND + d] * ev[d];
        l[e] = acc;
    }
    int i0 = 0;
#pragma unroll
    for (int e = 1; e < NE; e++) if (l[e] > l[i0]) i0 = e;
    int i1 = -1;
#pragma unroll
    for (int e = 0; e < NE; e++) if (e != i0 && (i1 < 0 || l[e] > l[i1])) i1 = e;
    float ex = __expf(l[i1] - l[i0]);   // l[i0] is the max
    float w0 = 1.f / (1.f + ex);
    g_ce[2 * b] = i0;     g_cw[2 * b] = w0;
    g_ce[2 * b + 1] = i1; g_cw[2 * b + 1] = ex * w0;
}

// ---- K2: Mt[e][f/2][g][f&1] = sum_d Wih0[e][g][d] * W_in[d][f]  (transposed layout) ----
__global__ void k_M(const float* __restrict__ Wih0, const float* __restrict__ W_in) {
    int e = blockIdx.x, g = blockIdx.y, f = threadIdx.x;
    if (f >= NF) return;
    float acc = 0.f;
    for (int d = 0; d < ND; d++) acc += Wih0[(e * 96 + g) * ND + d] * W_in[d * NF + f];
    g_Mt[((e * 25 + (f >> 1)) * 96 + g) * 2 + (f & 1)] = acc;
}

// ---- K3: chain constants: (b_in + emb[h_b]) . Wih0 + bih0 (+ bhh0 for r,z) ----
__global__ void k_c(const int* __restrict__ horizon, const float* __restrict__ b_in,
                    const float* __restrict__ emb, const float* __restrict__ Wih0,
                    const float* __restrict__ bih0, const float* __restrict__ bhh0) {
    int s = blockIdx.x, g = threadIdx.x;
    int b = s >> 1, e = g_ce[s];
    __shared__ float v[ND];
    if (g < ND) v[g] = b_in[g] + emb[(size_t)horizon[b] * ND + g];
    __syncthreads();
    float acc = bih0[e * 96 + g] + (g < 64 ? bhh0[e * 96 + g] : 0.f);  // bhh0_n stays with r*gh_n
#pragma unroll 8
    for (int d = 0; d < ND; d++) acc += Wih0[(e * 96 + g) * ND + d] * v[d];
    g_c[s * 96 + g] = acc;
}

// ---- K4: xg0 for BOTH chains of batch b in one block (shared x, coalesced Mt loads) ----
__global__ __launch_bounds__(96, 4) void k_xg0(const float* __restrict__ x) {
    int b = blockIdx.x, tile = blockIdx.y;
    int t0 = tile * TT;
    int tid = threadIdx.x;
    int e0 = g_ce[2 * b], e1 = g_ce[2 * b + 1];
    __shared__ __align__(16) float xs[TT * 52];   // 52-float row stride (16B-aligned rows)
    const float* xsrc = x + ((size_t)b * NL + t0) * NF;
    for (int idx = tid; idx < TT * NF; idx += 96)
        xs[(idx / NF) * 52 + (idx % NF)] = xsrc[idx];
    for (int r = tid; r < TT; r += 96) { xs[r * 52 + 50] = 0.f; xs[r * 52 + 51] = 0.f; }

    // coalesced: consecutive threads read consecutive float2 pairs
    const ull* Mt = (const ull*)g_Mt;
    ull ma[26], mb[26];
#pragma unroll
    for (int p = 0; p < 25; p++) {
        ma[p] = Mt[(e0 * 25 + p) * 96 + tid];
        mb[p] = Mt[(e1 * 25 + p) * 96 + tid];
    }
    ma[25] = 0ULL; mb[25] = 0ULL;   // pairs x pad (zeroed) contribute 0
    float ca = g_c[(2 * b) * 96 + tid];
    float cb = g_c[(2 * b + 1) * 96 + tid];
    __syncthreads();

    float* da = g_xg0 + ((size_t)(2 * b) * NL + t0) * 96 + tid;
    float* db = g_xg0 + ((size_t)(2 * b + 1) * NL + t0) * 96 + tid;
    for (int tt = 0; tt < TT; tt++) {
        const ulonglong2* x4 = (const ulonglong2*)(xs + tt * 52);
        ull a0 = 0, a1 = 0, a2 = 0, a3 = 0, b0 = 0, b1 = 0, b2 = 0, b3 = 0;
#pragma unroll
        for (int q = 0; q < 13; q++) {
            ulonglong2 v = x4[q];
            if (q & 1) {
                fma2(a2, ma[2 * q], v.x); fma2(a3, ma[2 * q + 1], v.y);
                fma2(b2, mb[2 * q], v.x); fma2(b3, mb[2 * q + 1], v.y);
            } else {
                fma2(a0, ma[2 * q], v.x); fma2(a1, ma[2 * q + 1], v.y);
                fma2(b0, mb[2 * q], v.x); fma2(b1, mb[2 * q + 1], v.y);
            }
        }
        da[(size_t)tt * 96] = (hsum2(a0) + hsum2(a1)) + (hsum2(a2) + hsum2(a3)) + ca;
        db[(size_t)tt * 96] = (hsum2(b0) + hsum2(b1)) + (hsum2(b2) + hsum2(b3)) + cb;
    }
}

// ---- K5: recurrent kernel. 1 block = 4 ARBITRARY chains, 12 warps (384 threads).
// warp = 4*stage + chain, so the 3 stage warps of chain c all land on SMSP c ->
// per-SMSP fma2 load perfectly balanced (144 fma2/step), all 4 SMSPs busy,
// single wave (128 blocks, 1 per SM).
//   stage 0: layer-0 cell for super-step k      (xg0 feeds from a 2-deep register
//            prefetch ring: loads for k+2 are issued at k -> ~2 super-steps of slack)
//   stage 1: Wih1 . h0 for super-step k-1       -> xgbuf[c][(k-1)&1]
//   stage 2: layer-1 cell for super-step k-2    reads xgbuf[c][(k-2)&1]
__global__ __launch_bounds__(384, 1) void k_rec(
    const float* __restrict__ Whh0, const float* __restrict__ bhh0,
    const float* __restrict__ Wih1, const float* __restrict__ Whh1,
    const float* __restrict__ bih1, const float* __restrict__ bhh1,
    const float* __restrict__ Wh1,  const float* __restrict__ bh1,
    const float* __restrict__ Wh2,  const float* __restrict__ bh2)
{
    int lane = threadIdx.x & 31;
    int warp = threadIdx.x >> 5;
    int chain = warp & 3;
    int stage = warp >> 2;           // 0,1,2
    int s = blockIdx.x * 4 + chain;  // global chain id
    int e = g_ce[s];

    __shared__ __align__(16) float h0buf[4][2][RR][32];
    __shared__ __align__(16) float xgbuf[4][2][RR][96];
    __shared__ __align__(16) float h1tmp[4][2][32];

    ull wreg[48];
    float cr = 0.f, cz = 0.f, cn = 0.f;
    const float* xg = g_xg0 + (size_t)s * NL * 96;
    float f0[3 * RR], f1[3 * RR];    // stage0: 2-deep feed prefetch ring

    {
        const float* Wbase = (stage == 0) ? (Whh0 + e * 96 * NH)
                           : (stage == 1) ? (Wih1 + e * 96 * NH)
                                          : (Whh1 + e * 96 * NH);
#pragma unroll
        for (int p = 0; p < 16; p++) {
            wreg[p]      = pack2(Wbase[lane * NH + 2 * p],        Wbase[lane * NH + 2 * p + 1]);
            wreg[16 + p] = pack2(Wbase[(32 + lane) * NH + 2 * p], Wbase[(32 + lane) * NH + 2 * p + 1]);
            wreg[32 + p] = pack2(Wbase[(64 + lane) * NH + 2 * p], Wbase[(64 + lane) * NH + 2 * p + 1]);
        }
        if (stage == 0) {
            cn = bhh0[e * 96 + 64 + lane];                      // bhh0_n (inside r*(.))
            h0buf[chain][1][RR - 1][lane] = 0.f;                // ring entry, read at k=0 j=0
            // feed prologue: super-steps 0 and 1 into the two ring buffers
#pragma unroll
            for (int j = 0; j < RR; j++) {
                const float* p = xg + (size_t)j * 96;
                f0[3 * j] = p[lane]; f0[3 * j + 1] = p[32 + lane]; f0[3 * j + 2] = p[64 + lane];
            }
#pragma unroll
            for (int j = 0; j < RR; j++) {
                const float* p = xg + (size_t)(RR + j) * 96;
                f1[3 * j] = p[lane]; f1[3 * j + 1] = p[32 + lane]; f1[3 * j + 2] = p[64 + lane];
            }
        } else if (stage == 1) {
            cr = bih1[e * 96 + lane]      + bhh1[e * 96 + lane];
            cz = bih1[e * 96 + 32 + lane] + bhh1[e * 96 + 32 + lane];
            cn = bih1[e * 96 + 64 + lane];
        } else {
            cn = bhh1[e * 96 + 64 + lane];                      // bhh1_n (inside r*(.))
            h1tmp[chain][1][lane] = 0.f;                        // parity ring entry
        }
    }
    __syncthreads();

    float h = 0.f;   // stage0: h0[lane]; stage2: h1[lane]

    for (int k = 0; k <= NK + 1; k++) {
        int buf = k & 1;
        if (stage == 0) {
            if (k < NK) {
                float* fc = (k & 1) ? f1 : f0;   // consume ring slot k&1
#pragma unroll
                for (int j = 0; j < RR; j++) {
                    const float* h2 = (j == 0) ? &h0buf[chain][buf ^ 1][RR - 1][0]
                                               : &h0buf[chain][buf][j - 1][0];
                    float gr, gz, gn;
                    matvec3(h2, wreg, gr, gz, gn);
                    float r = sigm(fc[3 * j] + gr);
                    float z = sigm(fc[3 * j + 1] + gz);
                    float n = tanh_f(fc[3 * j + 2] + r * (gn + cn));
                    h = (1.f - z) * n + z * h;
                    h0buf[chain][buf][j][lane] = h;
                    __syncwarp();
                }
                // refill this ring slot with feeds for super-step k+2
                if (k + 2 < NK) {
#pragma unroll
                    for (int j = 0; j < RR; j++) {
                        const float* p = xg + ((size_t)(k + 2) * RR + j) * 96;
                        fc[3 * j] = p[lane]; fc[3 * j + 1] = p[32 + lane]; fc[3 * j + 2] = p[64 + lane];
                    }
                }
            }
        } else if (stage == 1) {
            if (k >= 1 && k <= NK) {
                int kb = buf ^ 1;   // (k-1)&1
#pragma unroll
                for (int j = 0; j < RR; j++) {
                    float gr, gz, gn;
                    matvec3(&h0buf[chain][kb][j][0], wreg, gr, gz, gn);
                    xgbuf[chain][kb][j][lane]      = gr + cr;
                    xgbuf[chain][kb][j][32 + lane] = gz + cz;
                    xgbuf[chain][kb][j][64 + lane] = gn + cn;
                }
            }
        } else {
            if (k >= 2) {
                int kb = buf;       // (k-2)&1
#pragma unroll
                for (int j = 0; j < RR; j++) {
                    float fr_ = xgbuf[chain][kb][j][lane];
                    float fz_ = xgbuf[chain][kb][j][32 + lane];
                    float fn_ = xgbuf[chain][kb][j][64 + lane];
                    float gr, gz, gn;
                    matvec3(&h1tmp[chain][(j & 1) ^ 1][0], wreg, gr, gz, gn);
                    float r = sigm(fr_ + gr);
                    float z = sigm(fz_ + gz);
                    float n = tanh_f(fn_ + r * (gn + cn));
                    h = (1.f - z) * n + z * h;
                    h1tmp[chain][j & 1][lane] = h;
                    __syncwarp();
                }
            }
        }
        __syncthreads();
    }

    // final h1 in h1tmp[chain][1] (t=1799 has parity 1); last barrier published it.
    // stage0 warps (0..3) each handle their chain's head MLP.
    if (stage == 0) {
        const float* h1 = &h1tmp[chain][1][0];
        float acc = bh1[e * 32 + lane];
#pragma unroll
        for (int j = 0; j < NH; j++) acc += Wh1[(e * 32 + lane) * NH + j] * h1[j];
        float hid = fmaxf(acc, 0.f);
        float v = Wh2[e * 32 + lane] * hid;
#pragma unroll
        for (int off = 16; off > 0; off >>= 1) v += __shfl_down_sync(0xffffffffu, v, off);
        if (lane == 0) g_predw[s] = g_cw[s] * (v + bh2[e]);
    }
}

// ---- K6: combine the two routed chains per batch ----
__global__ void k_final(float* __restrict__ out) {
    int b = threadIdx.x;
    out[b] = g_predw[2 * b] + g_predw[2 * b + 1];
}

extern "C" void kernel_launch(void* const* d_in, const int* in_sizes, int n_in,
                              void* d_out, int out_size) {
    const float* x       = (const float*)d_in[0];
    const int*   horizon = (const int*)  d_in[1];
    const float* W_in    = (const float*)d_in[2];
    const float* b_in    = (const float*)d_in[3];
    const float* emb     = (const float*)d_in[4];
    const float* W_gate  = (const float*)d_in[5];
    const float* b_gate  = (const float*)d_in[6];
    const float* Wih0    = (const float*)d_in[7];
    const float* Whh0    = (const float*)d_in[8];
    const float* bih0    = (const float*)d_in[9];
    const float* bhh0    = (const float*)d_in[10];
    const float* Wih1    = (const float*)d_in[11];
    const float* Whh1    = (const float*)d_in[12];
    const float* bih1    = (const float*)d_in[13];
    const float* bhh1    = (const float*)d_in[14];
    const float* Wh1     = (const float*)d_in[15];
    const float* bh1     = (const float*)d_in[16];
    const float* Wh2     = (const float*)d_in[17];
    const float* bh2     = (const float*)d_in[18];
    float* out = (float*)d_out;

    k_gate<<<1, NB>>>(horizon, emb, W_gate, b_gate);
    k_M<<<dim3(NE, 96), 64>>>(Wih0, W_in);
    k_c<<<NS, 96>>>(horizon, b_in, emb, Wih0, bih0, bhh0);
    k_xg0<<<dim3(NB, NTILE), 96>>>(x);
    k_rec<<<NS / 4, 384>>>(Whh0, bhh0, Wih1, Whh1, bih1, bhh1, Wh1, bh1, Wh2, bh2);
    k_final<<<1, NB>>>(out);
}

// round 15
// speedup vs baseline: 1.7336x; 1.3526x over previous
#include <cuda_runtime.h>
#include <cstdint>

// MoEGRU: B=256, L=1800, F=50, E=4, K=2, H=32, D=64, HU=32
#define NB 256
#define NL 1800
#define NF 50
#define NE 4
#define NH 32
#define ND 64
#define NS 512       // routed chains = B*K
#define TT 40        // time-tile for xg0 GEMM
#define NTILE 45     // 1800/40
#define RR 6         // recurrence pipeline batch (even, divides NL)
#define NK (NL / RR) // 300 super-steps

typedef unsigned long long ull;

// ---- scratch (static device globals; no allocation allowed) ----
__device__ float g_xg0[(size_t)NS * NL * 96];   // precomputed input gates, layer 0
__device__ float g_Mt[NE * 25 * 96 * 2];        // fused W_in->Wih0, transposed+pair-packed
__device__ float g_c[NS * 96];                  // per-chain constant (emb/bias folded)
__device__ int   g_ce[NS];                      // chain -> expert
__device__ float g_cw[NS];                      // chain -> routing weight
__device__ float g_predw[NS];                   // weighted per-chain prediction

// ---- packed f32x2 helpers (sm_103a dual-fp32 pipe) ----
__device__ __forceinline__ ull pack2(float lo, float hi) {
    ull r;
    asm("mov.b64 %0, {%1, %2};" : "=l"(r) : "f"(lo), "f"(hi));
    return r;
}
__device__ __forceinline__ void fma2(ull &acc, ull a, ull b) {
    asm("fma.rn.f32x2 %0, %1, %2, %0;" : "+l"(acc) : "l"(a), "l"(b));
}
__device__ __forceinline__ float hsum2(ull v) {
    float lo, hi;
    asm("mov.b64 {%0, %1}, %2;" : "=f"(lo), "=f"(hi) : "l"(v));
    return lo + hi;
}

// fast activations: MUFU.RCP instead of IEEE divide
__device__ __forceinline__ float frcp(float x) {
    float r;
    asm("rcp.approx.f32 %0, %1;" : "=f"(r) : "f"(x));
    return r;
}
__device__ __forceinline__ float sigm(float x) { return frcp(1.f + __expf(-x)); }
__device__ __forceinline__ float tanh_f(float x) {
    return fmaf(-2.f, frcp(1.f + __expf(2.f * x)), 1.f);
}

// single-chain 96x32 matvec: weights W[0:16)=r, [16:32)=z, [32:48)=n
__device__ __forceinline__ void matvec3(const float* __restrict__ h,
                                        const ull* W,
                                        float& gr, float& gz, float& gn) {
    const ulonglong2* h4 = (const ulonglong2*)h;
    ull ar = 0, az = 0, an = 0;
#pragma unroll
    for (int p = 0; p < 8; p++) {
        ulonglong2 v = h4[p];
        fma2(ar, W[2 * p], v.x);      fma2(ar, W[2 * p + 1], v.y);
        fma2(az, W[16 + 2 * p], v.x); fma2(az, W[16 + 2 * p + 1], v.y);
        fma2(an, W[32 + 2 * p], v.x); fma2(an, W[32 + 2 * p + 1], v.y);
    }
    gr = hsum2(ar); gz = hsum2(az); gn = hsum2(an);
}

// ---- K1: gating (top-2 softmax) ----
__global__ void k_gate(const int* __restrict__ horizon, const float* __restrict__ emb,
                       const float* __restrict__ W_gate, const float* __restrict__ b_gate) {
    int b = threadIdx.x;
    const float* ev = emb + (size_t)horizon[b] * ND;
    float l[NE];
#pragma unroll
    for (int e = 0; e < NE; e++) {
        float acc = b_gate[e];
        for (int d = 0; d < ND; d++) acc += W_gate[e * ND + d] * ev[d];
        l[e] = acc;
    }
    int i0 = 0;
#pragma unroll
    for (int e = 1; e < NE; e++) if (l[e] > l[i0]) i0 = e;
    int i1 = -1;
#pragma unroll
    for (int e = 0; e < NE; e++) if (e != i0 && (i1 < 0 || l[e] > l[i1])) i1 = e;
    float ex = __expf(l[i1] - l[i0]);   // l[i0] is the max
    float w0 = 1.f / (1.f + ex);
    g_ce[2 * b] = i0;     g_cw[2 * b] = w0;
    g_ce[2 * b + 1] = i1; g_cw[2 * b + 1] = ex * w0;
}

// ---- K2: Mt[e][f/2][g][f&1] = sum_d Wih0[e][g][d] * W_in[d][f]  (transposed layout) ----
__global__ void k_M(const float* __restrict__ Wih0, const float* __restrict__ W_in) {
    int e = blockIdx.x, g = blockIdx.y, f = threadIdx.x;
    if (f >= NF) return;
    float acc = 0.f;
    for (int d = 0; d < ND; d++) acc += Wih0[(e * 96 + g) * ND + d] * W_in[d * NF + f];
    g_Mt[((e * 25 + (f >> 1)) * 96 + g) * 2 + (f & 1)] = acc;
}

// ---- K3: chain constants: (b_in + emb[h_b]) . Wih0 + bih0 (+ bhh0 for r,z) ----
__global__ void k_c(const int* __restrict__ horizon, const float* __restrict__ b_in,
                    const float* __restrict__ emb, const float* __restrict__ Wih0,
                    const float* __restrict__ bih0, const float* __restrict__ bhh0) {
    int s = blockIdx.x, g = threadIdx.x;
    int b = s >> 1, e = g_ce[s];
    __shared__ float v[ND];
    if (g < ND) v[g] = b_in[g] + emb[(size_t)horizon[b] * ND + g];
    __syncthreads();
    float acc = bih0[e * 96 + g] + (g < 64 ? bhh0[e * 96 + g] : 0.f);  // bhh0_n stays with r*gh_n
#pragma unroll 8
    for (int d = 0; d < ND; d++) acc += Wih0[(e * 96 + g) * ND + d] * v[d];
    g_c[s * 96 + g] = acc;
}

// ---- K4: xg0 for BOTH chains of batch b in one block (shared x, coalesced Mt loads) ----
__global__ __launch_bounds__(96, 4) void k_xg0(const float* __restrict__ x) {
    int b = blockIdx.x, tile = blockIdx.y;
    int t0 = tile * TT;
    int tid = threadIdx.x;
    int e0 = g_ce[2 * b], e1 = g_ce[2 * b + 1];
    __shared__ __align__(16) float xs[TT * 52];   // 52-float row stride (16B-aligned rows)
    const float* xsrc = x + ((size_t)b * NL + t0) * NF;
    for (int idx = tid; idx < TT * NF; idx += 96)
        xs[(idx / NF) * 52 + (idx % NF)] = xsrc[idx];
    for (int r = tid; r < TT; r += 96) { xs[r * 52 + 50] = 0.f; xs[r * 52 + 51] = 0.f; }

    // coalesced: consecutive threads read consecutive float2 pairs
    const ull* Mt = (const ull*)g_Mt;
    ull ma[26], mb[26];
#pragma unroll
    for (int p = 0; p < 25; p++) {
        ma[p] = Mt[(e0 * 25 + p) * 96 + tid];
        mb[p] = Mt[(e1 * 25 + p) * 96 + tid];
    }
    ma[25] = 0ULL; mb[25] = 0ULL;   // pairs x pad (zeroed) contribute 0
    float ca = g_c[(2 * b) * 96 + tid];
    float cb = g_c[(2 * b + 1) * 96 + tid];
    __syncthreads();

    float* da = g_xg0 + ((size_t)(2 * b) * NL + t0) * 96 + tid;
    float* db = g_xg0 + ((size_t)(2 * b + 1) * NL + t0) * 96 + tid;
    for (int tt = 0; tt < TT; tt++) {
        const ulonglong2* x4 = (const ulonglong2*)(xs + tt * 52);
        ull a0 = 0, a1 = 0, a2 = 0, a3 = 0, b0 = 0, b1 = 0, b2 = 0, b3 = 0;
#pragma unroll
        for (int q = 0; q < 13; q++) {
            ulonglong2 v = x4[q];
            if (q & 1) {
                fma2(a2, ma[2 * q], v.x); fma2(a3, ma[2 * q + 1], v.y);
                fma2(b2, mb[2 * q], v.x); fma2(b3, mb[2 * q + 1], v.y);
            } else {
                fma2(a0, ma[2 * q], v.x); fma2(a1, ma[2 * q + 1], v.y);
                fma2(b0, mb[2 * q], v.x); fma2(b1, mb[2 * q + 1], v.y);
            }
        }
        da[(size_t)tt * 96] = (hsum2(a0) + hsum2(a1)) + (hsum2(a2) + hsum2(a3)) + ca;
        db[(size_t)tt * 96] = (hsum2(b0) + hsum2(b1)) + (hsum2(b2) + hsum2(b3)) + cb;
    }
}

// ---- K5: recurrent kernel. 1 block = 4 chains, 12 warps (384 threads), 1 block/SM.
// warp = 4*stage + chain: the 3 stage warps of chain c all land on SMSP c ->
// per-SMSP fma2 load balanced (144 fma2/step), all 4 SMSPs busy, single wave.
// Register budget (cap 170 @384thr): NO feed ring in stage0 (that spilled in R14).
//   stage 0: layer-0 cell for super-step k      reads x0buf[c][k&1]      -> h0buf[c][k&1]
//   stage 1: Wih1 . h0 for super-step k-1       -> xgbuf[c][(k-1)&1]; ALSO prefetches
//            xg0 feeds for super-step k+1 (LDG early, STS x0buf[c][(k+1)&1] late;
//            one full window ~1700cyc of slack >> 577cyc DRAM latency)
//   stage 2: layer-1 cell for super-step k-2    reads xgbuf[c][(k-2)&1]
__global__ __launch_bounds__(384, 1) void k_rec(
    const float* __restrict__ Whh0, const float* __restrict__ bhh0,
    const float* __restrict__ Wih1, const float* __restrict__ Whh1,
    const float* __restrict__ bih1, const float* __restrict__ bhh1,
    const float* __restrict__ Wh1,  const float* __restrict__ bh1,
    const float* __restrict__ Wh2,  const float* __restrict__ bh2)
{
    int lane = threadIdx.x & 31;
    int warp = threadIdx.x >> 5;
    int chain = warp & 3;
    int stage = warp >> 2;           // 0,1,2
    int s = blockIdx.x * 4 + chain;  // global chain id
    int e = g_ce[s];

    __shared__ __align__(16) float h0buf[4][2][RR][32];
    __shared__ __align__(16) float xgbuf[4][2][RR][96];
    __shared__ __align__(16) float x0buf[4][2][RR][96];
    __shared__ __align__(16) float h1tmp[4][2][32];

    ull wreg[48];
    float cr = 0.f, cz = 0.f, cn = 0.f;
    const float* xg = g_xg0 + (size_t)s * NL * 96;

    {
        const float* Wbase = (stage == 0) ? (Whh0 + e * 96 * NH)
                           : (stage == 1) ? (Wih1 + e * 96 * NH)
                                          : (Whh1 + e * 96 * NH);
#pragma unroll
        for (int p = 0; p < 16; p++) {
            wreg[p]      = pack2(Wbase[lane * NH + 2 * p],        Wbase[lane * NH + 2 * p + 1]);
            wreg[16 + p] = pack2(Wbase[(32 + lane) * NH + 2 * p], Wbase[(32 + lane) * NH + 2 * p + 1]);
            wreg[32 + p] = pack2(Wbase[(64 + lane) * NH + 2 * p], Wbase[(64 + lane) * NH + 2 * p + 1]);
        }
        if (stage == 0) {
            cn = bhh0[e * 96 + 64 + lane];                      // bhh0_n (inside r*(.))
            h0buf[chain][1][RR - 1][lane] = 0.f;                // ring entry, read at k=0 j=0
        } else if (stage == 1) {
            cr = bih1[e * 96 + lane]      + bhh1[e * 96 + lane];
            cz = bih1[e * 96 + 32 + lane] + bhh1[e * 96 + 32 + lane];
            cn = bih1[e * 96 + 64 + lane];
            // feed prologue: super-step 0 directly into x0buf[.][0]
#pragma unroll
            for (int j = 0; j < RR; j++) {
                const float* p = xg + (size_t)j * 96;
                x0buf[chain][0][j][lane]      = p[lane];
                x0buf[chain][0][j][32 + lane] = p[32 + lane];
                x0buf[chain][0][j][64 + lane] = p[64 + lane];
            }
        } else {
            cn = bhh1[e * 96 + 64 + lane];                      // bhh1_n (inside r*(.))
            h1tmp[chain][1][lane] = 0.f;                        // parity ring entry
        }
    }
    __syncthreads();

    float h = 0.f;   // stage0: h0[lane]; stage2: h1[lane]

    for (int k = 0; k <= NK + 1; k++) {
        int buf = k & 1;
        if (stage == 0) {
            if (k < NK) {
#pragma unroll
                for (int j = 0; j < RR; j++) {
                    float xr = x0buf[chain][buf][j][lane];
                    float xz = x0buf[chain][buf][j][32 + lane];
                    float xn = x0buf[chain][buf][j][64 + lane];
                    const float* h2 = (j == 0) ? &h0buf[chain][buf ^ 1][RR - 1][0]
                                               : &h0buf[chain][buf][j - 1][0];
                    float gr, gz, gn;
                    matvec3(h2, wreg, gr, gz, gn);
                    float r = sigm(xr + gr);
                    float z = sigm(xz + gz);
                    float n = tanh_f(xn + r * (gn + cn));
                    h = (1.f - z) * n + z * h;
                    h0buf[chain][buf][j][lane] = h;
                    __syncwarp();
                }
            }
        } else if (stage == 1) {
            // issue feed LDGs FIRST so their latency hides under the matvec work
            float tr[RR], tz[RR], tn[RR];
            bool dofeed = (k + 1 < NK);
            if (dofeed) {
#pragma unroll
                for (int j = 0; j < RR; j++) {
                    const float* p = xg + ((size_t)(k + 1) * RR + j) * 96;
                    tr[j] = p[lane]; tz[j] = p[32 + lane]; tn[j] = p[64 + lane];
                }
            }
            if (k >= 1 && k <= NK) {
                int kb = buf ^ 1;   // (k-1)&1
#pragma unroll
                for (int j = 0; j < RR; j++) {
                    float gr, gz, gn;
                    matvec3(&h0buf[chain][kb][j][0], wreg, gr, gz, gn);
                    xgbuf[chain][kb][j][lane]      = gr + cr;
                    xgbuf[chain][kb][j][32 + lane] = gz + cz;
                    xgbuf[chain][kb][j][64 + lane] = gn + cn;
                }
            }
            if (dofeed) {
                int nb = buf ^ 1;   // (k+1)&1
#pragma unroll
                for (int j = 0; j < RR; j++) {
                    x0buf[chain][nb][j][lane]      = tr[j];
                    x0buf[chain][nb][j][32 + lane] = tz[j];
                    x0buf[chain][nb][j][64 + lane] = tn[j];
                }
            }
        } else {
            if (k >= 2) {
                int kb = buf;       // (k-2)&1
#pragma unroll
                for (int j = 0; j < RR; j++) {
                    float fr_ = xgbuf[chain][kb][j][lane];
                    float fz_ = xgbuf[chain][kb][j][32 + lane];
                    float fn_ = xgbuf[chain][kb][j][64 + lane];
                    float gr, gz, gn;
                    matvec3(&h1tmp[chain][(j & 1) ^ 1][0], wreg, gr, gz, gn);
                    float r = sigm(fr_ + gr);
                    float z = sigm(fz_ + gz);
                    float n = tanh_f(fn_ + r * (gn + cn));
                    h = (1.f - z) * n + z * h;
                    h1tmp[chain][j & 1][lane] = h;
                    __syncwarp();
                }
            }
        }
        __syncthreads();
    }

    // final h1 in h1tmp[chain][1] ((RR-1)&1 == 1); last barrier published it.
    // stage0 warps (0..3) each handle their chain's head MLP.
    if (stage == 0) {
        const float* h1 = &h1tmp[chain][1][0];
        float acc = bh1[e * 32 + lane];
#pragma unroll
        for (int j = 0; j < NH; j++) acc += Wh1[(e * 32 + lane) * NH + j] * h1[j];
        float hid = fmaxf(acc, 0.f);
        float v = Wh2[e * 32 + lane] * hid;
#pragma unroll
        for (int off = 16; off > 0; off >>= 1) v += __shfl_down_sync(0xffffffffu, v, off);
        if (lane == 0) g_predw[s] = g_cw[s] * (v + bh2[e]);
    }
}

// ---- K6: combine the two routed chains per batch ----
__global__ void k_final(float* __restrict__ out) {
    int b = threadIdx.x;
    out[b] = g_predw[2 * b] + g_predw[2 * b + 1];
}

extern "C" void kernel_launch(void* const* d_in, const int* in_sizes, int n_in,
                              void* d_out, int out_size) {
    const float* x       = (const float*)d_in[0];
    const int*   horizon = (const int*)  d_in[1];
    const float* W_in    = (const float*)d_in[2];
    const float* b_in    = (const float*)d_in[3];
    const float* emb     = (const float*)d_in[4];
    const float* W_gate  = (const float*)d_in[5];
    const float* b_gate  = (const float*)d_in[6];
    const float* Wih0    = (const float*)d_in[7];
    const float* Whh0    = (const float*)d_in[8];
    const float* bih0    = (const float*)d_in[9];
    const float* bhh0    = (const float*)d_in[10];
    const float* Wih1    = (const float*)d_in[11];
    const float* Whh1    = (const float*)d_in[12];
    const float* bih1    = (const float*)d_in[13];
    const float* bhh1    = (const float*)d_in[14];
    const float* Wh1     = (const float*)d_in[15];
    const float* bh1     = (const float*)d_in[16];
    const float* Wh2     = (const float*)d_in[17];
    const float* bh2     = (const float*)d_in[18];
    float* out = (float*)d_out;

    k_gate<<<1, NB>>>(horizon, emb, W_gate, b_gate);
    k_M<<<dim3(NE, 96), 64>>>(Wih0, W_in);
    k_c<<<NS, 96>>>(horizon, b_in, emb, Wih0, bih0, bhh0);
    k_xg0<<<dim3(NB, NTILE), 96>>>(x);
    k_rec<<<NS / 4, 384>>>(Whh0, bhh0, Wih1, Whh1, bih1, bhh1, Wh1, bh1, Wh2, bh2);
    k_final<<<1, NB>>>(out);
}